// round 4
// baseline (speedup 1.0000x reference)
#include <cuda_runtime.h>
#include <cuda_bf16.h>
#include <cstdint>

// Scratch (no allocs allowed): module-scope device globals.
#define MAXN (1 << 17)          // 131072 >= N=100000
__device__ int   g_deg_out[MAXN];
__device__ int   g_deg_in [MAXN];
__device__ float g_dinv_out[MAXN];
__device__ float g_dinv_in [MAXN];
__device__ float g_xw [(size_t)MAXN * 64];   // x @ W^T
__device__ float g_agg[(size_t)MAXN * 64];   // accumulation target

// ---------------------------------------------------------------------------
// 1) zero degree counters + agg accumulator
__global__ void k_zero(int N) {
    int i = blockIdx.x * blockDim.x + threadIdx.x;
    if (i < N) { g_deg_out[i] = 0; g_deg_in[i] = 0; }
    int total4 = N * 16;
    for (int j = i; j < total4; j += gridDim.x * blockDim.x)
        ((float4*)g_agg)[j] = make_float4(0.f, 0.f, 0.f, 0.f);
}

// 2) count degrees (one thread per edge). edge_index is INT32 (JAX default
//    x64-disabled demotes the reference's int64 to int32).
__global__ void k_count_deg(const int* __restrict__ ei, int E) {
    int e = blockIdx.x * blockDim.x + threadIdx.x;
    if (e < E) {
        atomicAdd(&g_deg_out[ei[e]], 1);        // row = dst
        atomicAdd(&g_deg_in [ei[E + e]], 1);    // col = src
    }
}

// 3) deg -> rsqrt(max(deg,1))
__global__ void k_dinv(int N) {
    int i = blockIdx.x * blockDim.x + threadIdx.x;
    if (i < N) {
        int d_o = g_deg_out[i]; if (d_o < 1) d_o = 1;
        int d_i = g_deg_in [i]; if (d_i < 1) d_i = 1;
        g_dinv_out[i] = rsqrtf((float)d_o);
        g_dinv_in [i] = rsqrtf((float)d_i);
    }
}

// 4) x' = x @ W^T   (N x 64) = (N x 64)(64 x 64)^T
//    Block: 64 rows x 64 cols. 256 threads, each computes a 4x4 register tile.
__global__ __launch_bounds__(256) void k_gemm_xw(
    const float* __restrict__ x, const float* __restrict__ W, int N)
{
    __shared__ float4 Wt[64][16];     // Wt[i][og] = {W[4og+0..3][i]}
    __shared__ float  xs[64][65];     // padded

    int tid = threadIdx.x;
    int rg  = tid >> 4;               // 0..15 row-group (4 rows each)
    int og  = tid & 15;               // 0..15 col-group (4 cols each)
    int row0 = blockIdx.x * 64;

    #pragma unroll
    for (int idx = tid; idx < 64 * 16; idx += 256) {
        int i = idx >> 4, g = idx & 15;
        float4 w;
        w.x = W[(4 * g + 0) * 64 + i];
        w.y = W[(4 * g + 1) * 64 + i];
        w.z = W[(4 * g + 2) * 64 + i];
        w.w = W[(4 * g + 3) * 64 + i];
        Wt[i][g] = w;
    }
    #pragma unroll
    for (int idx = tid; idx < 64 * 64; idx += 256) {
        int r = idx >> 6, i = idx & 63;
        int gr = row0 + r;
        xs[r][i] = (gr < N) ? x[(size_t)gr * 64 + i] : 0.0f;
    }
    __syncthreads();

    float4 acc[4];
    #pragma unroll
    for (int j = 0; j < 4; j++) acc[j] = make_float4(0.f, 0.f, 0.f, 0.f);

    #pragma unroll
    for (int i = 0; i < 64; i++) {
        float4 w = Wt[i][og];
        #pragma unroll
        for (int j = 0; j < 4; j++) {
            float xv = xs[rg * 4 + j][i];
            acc[j].x += xv * w.x;
            acc[j].y += xv * w.y;
            acc[j].z += xv * w.z;
            acc[j].w += xv * w.w;
        }
    }

    #pragma unroll
    for (int j = 0; j < 4; j++) {
        int r = row0 + rg * 4 + j;
        if (r < N)
            *(float4*)(g_xw + (size_t)r * 64 + og * 4) = acc[j];
    }
}

// 5) scatter: g_agg[row] += w_e * x'[col].  16 lanes per edge; 4 scalar
//    atomicAdd (-> REDG.ADD.F32, result unused) per lane.
__global__ __launch_bounds__(256) void k_aggregate(
    const int* __restrict__ ei, int E)
{
    int t = blockIdx.x * blockDim.x + threadIdx.x;
    int e    = t >> 4;
    int lane = t & 15;
    if (e >= E) return;

    int row = ei[e];        // dst
    int col = ei[E + e];    // src
    float w = g_dinv_out[row] * g_dinv_in[col];

    const float4 v = *(const float4*)(g_xw + (size_t)col * 64 + lane * 4);
    float* dst = g_agg + (size_t)row * 64 + lane * 4;
    atomicAdd(dst + 0, w * v.x);
    atomicAdd(dst + 1, w * v.y);
    atomicAdd(dst + 2, w * v.z);
    atomicAdd(dst + 3, w * v.w);
}

// 6) out = agg + bias (plain stores to d_out)
__global__ void k_finalize(float* __restrict__ out, const float* __restrict__ b, int total4) {
    int idx = blockIdx.x * blockDim.x + threadIdx.x;
    if (idx >= total4) return;
    float4 a = ((const float4*)g_agg)[idx];
    int d4 = (idx & 15) * 4;                // feature offset 0..60
    a.x += b[d4 + 0]; a.y += b[d4 + 1]; a.z += b[d4 + 2]; a.w += b[d4 + 3];
    ((float4*)out)[idx] = a;
}

// ---------------------------------------------------------------------------
extern "C" void kernel_launch(void* const* d_in, const int* in_sizes, int n_in,
                              void* d_out, int out_size)
{
    const float* x  = (const float*)d_in[0];
    const int*   ei = (const int*)d_in[1];     // int32! (JAX x64 disabled)
    const float* W  = (const float*)d_in[2];
    const float* b  = (const float*)d_in[3];
    float*       out = (float*)d_out;

    int N = in_sizes[0] / 64;
    int E = in_sizes[1] / 2;

    k_zero     <<<(N + 255) / 256, 256>>>(N);
    k_count_deg<<<(E + 255) / 256, 256>>>(ei, E);
    k_dinv     <<<(N + 255) / 256, 256>>>(N);
    k_gemm_xw  <<<(N + 63) / 64, 256>>>(x, W, N);
    k_aggregate<<<((E * 16) + 255) / 256, 256>>>(ei, E);
    k_finalize <<<(N * 16 + 255) / 256, 256>>>(out, b, N * 16);
}

// round 5
// speedup vs baseline: 2.0727x; 2.0727x over previous
#include <cuda_runtime.h>
#include <cuda_bf16.h>
#include <cstdint>

#define MAXN (1 << 17)          // 131072 >= N=100000
#define MAXE (1 << 21)          // 2097152 >= E=1600000
#define NB_MAX 512              // max scan blocks: ceil(131072/256)=512

__device__ int   g_deg_out[MAXN];
__device__ int   g_deg_in [MAXN];
__device__ float g_dinv_out[MAXN];
__device__ float g_dinv_in [MAXN];
__device__ int   g_rows  [MAXN + 1];   // exclusive CSR row starts
__device__ int   g_cursor[MAXN];
__device__ int   g_bsum  [NB_MAX];
__device__ int   g_csr_col[MAXE];
__device__ float g_csr_w  [MAXE];
__device__ float g_xw[(size_t)MAXN * 64];   // x @ W^T

// ---------------------------------------------------------------------------
__global__ void k_zero(int N) {
    int i = blockIdx.x * blockDim.x + threadIdx.x;
    if (i < N) { g_deg_out[i] = 0; g_deg_in[i] = 0; g_cursor[i] = 0; }
}

__global__ void k_count_deg(const int* __restrict__ ei, int E) {
    int e = blockIdx.x * blockDim.x + threadIdx.x;
    if (e < E) {
        atomicAdd(&g_deg_out[ei[e]], 1);        // row = dst
        atomicAdd(&g_deg_in [ei[E + e]], 1);    // col = src
    }
}

__global__ void k_dinv(int N) {
    int i = blockIdx.x * blockDim.x + threadIdx.x;
    if (i < N) {
        int d_o = g_deg_out[i]; if (d_o < 1) d_o = 1;
        int d_i = g_deg_in [i]; if (d_i < 1) d_i = 1;
        g_dinv_out[i] = rsqrtf((float)d_o);
        g_dinv_in [i] = rsqrtf((float)d_i);
    }
}

// --- exclusive prefix sum of g_deg_out -> g_rows --------------------------
__global__ void k_scan1(int N) {                 // block-local scan
    __shared__ int s[256];
    int t = threadIdx.x;
    int i = blockIdx.x * 256 + t;
    int v = (i < N) ? g_deg_out[i] : 0;
    s[t] = v;
    __syncthreads();
    #pragma unroll
    for (int off = 1; off < 256; off <<= 1) {
        int add = (t >= off) ? s[t - off] : 0;
        __syncthreads();
        s[t] += add;
        __syncthreads();
    }
    if (i <= N) g_rows[i] = s[t] - v;            // block-local exclusive
    if (t == 255) g_bsum[blockIdx.x] = s[255];
}

__global__ void k_scan2(int nblocks) {           // scan of block sums (1 block)
    __shared__ int s[NB_MAX];
    int t = threadIdx.x;
    int v = (t < nblocks) ? g_bsum[t] : 0;
    s[t] = v;
    __syncthreads();
    #pragma unroll
    for (int off = 1; off < NB_MAX; off <<= 1) {
        int add = (t >= off) ? s[t - off] : 0;
        __syncthreads();
        s[t] += add;
        __syncthreads();
    }
    g_bsum[t] = s[t] - v;                        // exclusive
}

__global__ void k_scan3(int N, int E) {          // add block offsets
    int i = blockIdx.x * blockDim.x + threadIdx.x;
    if (i < N) g_rows[i] += g_bsum[i >> 8];
    if (i == 0) g_rows[N] = E;
}

// --- scatter edges into CSR (int atomics only, spread addresses) ----------
__global__ void k_scatter(const int* __restrict__ ei, int E) {
    int e = blockIdx.x * blockDim.x + threadIdx.x;
    if (e >= E) return;
    int row = ei[e];
    int col = ei[E + e];
    int pos = g_rows[row] + atomicAdd(&g_cursor[row], 1);
    g_csr_col[pos] = col;
    g_csr_w  [pos] = g_dinv_in[col];
}

// --- x' = x @ W^T  (64x64 tile per block, float4 LDS on both operands) ----
__global__ __launch_bounds__(256) void k_gemm_xw(
    const float* __restrict__ x, const float* __restrict__ W, int N)
{
    __shared__ float4 Wt[64][16];      // Wt[i][og] = {W[4og+0..3][i]}
    __shared__ float  xs[64][68];      // row stride 68 floats (16B aligned)

    int tid = threadIdx.x;
    int rg  = tid >> 4;                // 0..15
    int og  = tid & 15;                // 0..15
    int row0 = blockIdx.x * 64;

    #pragma unroll
    for (int idx = tid; idx < 64 * 16; idx += 256) {
        int i = idx >> 4, g = idx & 15;
        float4 w;
        w.x = W[(4 * g + 0) * 64 + i];
        w.y = W[(4 * g + 1) * 64 + i];
        w.z = W[(4 * g + 2) * 64 + i];
        w.w = W[(4 * g + 3) * 64 + i];
        Wt[i][g] = w;
    }
    #pragma unroll
    for (int idx = tid; idx < 64 * 16; idx += 256) {
        int r = idx >> 4, c4 = idx & 15;
        int gr = row0 + r;
        float4 v = (gr < N) ? *(const float4*)(x + (size_t)gr * 64 + c4 * 4)
                            : make_float4(0.f, 0.f, 0.f, 0.f);
        *(float4*)&xs[r][c4 * 4] = v;
    }
    __syncthreads();

    float4 acc[4];
    #pragma unroll
    for (int j = 0; j < 4; j++) acc[j] = make_float4(0.f, 0.f, 0.f, 0.f);

    #pragma unroll
    for (int i = 0; i < 64; i += 4) {
        float4 w0 = Wt[i + 0][og];
        float4 w1 = Wt[i + 1][og];
        float4 w2 = Wt[i + 2][og];
        float4 w3 = Wt[i + 3][og];
        #pragma unroll
        for (int j = 0; j < 4; j++) {
            float4 xv = *(const float4*)&xs[rg * 4 + j][i];
            acc[j].x += xv.x * w0.x + xv.y * w1.x + xv.z * w2.x + xv.w * w3.x;
            acc[j].y += xv.x * w0.y + xv.y * w1.y + xv.z * w2.y + xv.w * w3.y;
            acc[j].z += xv.x * w0.z + xv.y * w1.z + xv.z * w2.z + xv.w * w3.z;
            acc[j].w += xv.x * w0.w + xv.y * w1.w + xv.z * w2.w + xv.w * w3.w;
        }
    }

    #pragma unroll
    for (int j = 0; j < 4; j++) {
        int r = row0 + rg * 4 + j;
        if (r < N)
            *(float4*)(g_xw + (size_t)r * 64 + og * 4) = acc[j];
    }
}

// --- CSR aggregation, fused bias + direct d_out write ---------------------
// 16 lanes per dst node; each lane owns 4 features (float4 accumulator).
__global__ __launch_bounds__(256) void k_agg_csr(
    float* __restrict__ out, const float* __restrict__ b, int N)
{
    int t    = blockIdx.x * 256 + threadIdx.x;
    int n    = t >> 4;
    int lane = t & 15;
    if (n >= N) return;

    int start = g_rows[n];
    int end   = g_rows[n + 1];

    float4 acc = make_float4(0.f, 0.f, 0.f, 0.f);
    for (int j = start; j < end; j++) {
        int   col = g_csr_col[j];               // broadcast within 16 lanes
        float w   = g_csr_w[j];
        float4 v  = *(const float4*)(g_xw + (size_t)col * 64 + lane * 4);
        acc.x += w * v.x;
        acc.y += w * v.y;
        acc.z += w * v.z;
        acc.w += w * v.w;
    }

    float s = g_dinv_out[n];
    float4 bb = ((const float4*)b)[lane];
    float4 o;
    o.x = s * acc.x + bb.x;
    o.y = s * acc.y + bb.y;
    o.z = s * acc.z + bb.z;
    o.w = s * acc.w + bb.w;
    ((float4*)out)[(size_t)n * 16 + lane] = o;
}

// ---------------------------------------------------------------------------
extern "C" void kernel_launch(void* const* d_in, const int* in_sizes, int n_in,
                              void* d_out, int out_size)
{
    const float* x  = (const float*)d_in[0];
    const int*   ei = (const int*)d_in[1];     // int32 (JAX x64 disabled)
    const float* W  = (const float*)d_in[2];
    const float* b  = (const float*)d_in[3];
    float*       out = (float*)d_out;

    int N = in_sizes[0] / 64;
    int E = in_sizes[1] / 2;
    int nblocks = (N + 255) / 256;

    k_zero     <<<(N + 255) / 256, 256>>>(N);
    k_count_deg<<<(E + 255) / 256, 256>>>(ei, E);
    k_dinv     <<<(N + 255) / 256, 256>>>(N);
    k_scan1    <<<nblocks, 256>>>(N);
    k_scan2    <<<1, NB_MAX>>>(nblocks);
    k_scan3    <<<(N + 255) / 256, 256>>>(N, E);
    k_scatter  <<<(E + 255) / 256, 256>>>(ei, E);
    k_gemm_xw  <<<(N + 63) / 64, 256>>>(x, W, N);
    k_agg_csr  <<<(N * 16 + 255) / 256, 256>>>(out, b, N);
}

// round 7
// speedup vs baseline: 2.3948x; 1.1554x over previous
#include <cuda_runtime.h>
#include <cuda_fp16.h>
#include <cstdint>

#define MAXN (1 << 17)          // 131072 >= N=100000
#define MAXE (1 << 21)          // 2097152 >= E=1600000
#define NB_MAX 512              // max scan blocks

__device__ int   g_deg_out[MAXN];
__device__ int   g_deg_in [MAXN];
__device__ float g_dinv_out[MAXN];
__device__ float g_dinv_in [MAXN];
__device__ int   g_rows  [MAXN + 1];   // exclusive CSR row starts
__device__ int   g_cursor[MAXN];
__device__ int   g_bsum  [NB_MAX];
__device__ uint2 g_csr   [MAXE];       // packed {col, w_bits}
__device__ uint2 g_xwh[(size_t)MAXN * 16];  // x @ W^T in fp16 (row=16 uint2=128B)

// ---------------------------------------------------------------------------
__global__ void k_zero(int N) {
    int i = blockIdx.x * blockDim.x + threadIdx.x;
    if (i < N) { g_deg_out[i] = 0; g_deg_in[i] = 0; g_cursor[i] = 0; }
}

__global__ void k_count_deg(const int* __restrict__ ei, int E) {
    int e = blockIdx.x * blockDim.x + threadIdx.x;
    if (e < E) {
        atomicAdd(&g_deg_out[ei[e]], 1);        // row = dst
        atomicAdd(&g_deg_in [ei[E + e]], 1);    // col = src
    }
}

// --- block-local exclusive scan of deg_out (shuffle-based) + dinv fused ---
__global__ __launch_bounds__(256) void k_scan1(int N) {
    int t = threadIdx.x;
    int i = blockIdx.x * 256 + t;
    int lane = t & 31, wid = t >> 5;

    int v = (i < N) ? g_deg_out[i] : 0;

    if (i < N) {                                 // fused dinv
        int d_o = v;            if (d_o < 1) d_o = 1;
        int d_i = g_deg_in[i];  if (d_i < 1) d_i = 1;
        g_dinv_out[i] = rsqrtf((float)d_o);
        g_dinv_in [i] = rsqrtf((float)d_i);
    }

    int s = v;                                   // warp inclusive scan
    #pragma unroll
    for (int off = 1; off < 32; off <<= 1) {
        int u = __shfl_up_sync(0xFFFFFFFFu, s, off);
        if (lane >= off) s += u;
    }
    __shared__ int wsum[8];
    if (lane == 31) wsum[wid] = s;
    __syncthreads();
    int base = 0;
    #pragma unroll
    for (int w = 0; w < 8; w++)
        if (w < wid) base += wsum[w];

    if (i < N) g_rows[i] = base + s - v;         // block-local exclusive
    if (t == 255) g_bsum[blockIdx.x] = base + s; // block total
}

// --- scan of block sums, 1 block of 512 (shuffle-based) -------------------
__global__ __launch_bounds__(NB_MAX) void k_scan2(int nblocks) {
    int t = threadIdx.x;
    int lane = t & 31, wid = t >> 5;
    int v = (t < nblocks) ? g_bsum[t] : 0;
    int s = v;
    #pragma unroll
    for (int off = 1; off < 32; off <<= 1) {
        int u = __shfl_up_sync(0xFFFFFFFFu, s, off);
        if (lane >= off) s += u;
    }
    __shared__ int wsum[16];
    if (lane == 31) wsum[wid] = s;
    __syncthreads();
    int base = 0;
    #pragma unroll
    for (int w = 0; w < 16; w++)
        if (w < wid) base += wsum[w];
    g_bsum[t] = base + s - v;                    // exclusive
}

__global__ void k_scan3(int N, int E) {
    int i = blockIdx.x * blockDim.x + threadIdx.x;
    if (i < N) g_rows[i] += g_bsum[i >> 8];
    if (i == 0) g_rows[N] = E;
}

// --- scatter edges into CSR: one packed 8B store per edge -----------------
__global__ void k_scatter(const int* __restrict__ ei, int E) {
    int e = blockIdx.x * blockDim.x + threadIdx.x;
    if (e >= E) return;
    int row = ei[e];
    int col = ei[E + e];
    int pos = g_rows[row] + atomicAdd(&g_cursor[row], 1);
    uint2 p;
    p.x = (unsigned)col;
    p.y = __float_as_uint(g_dinv_in[col]);
    g_csr[pos] = p;
}

// --- x' = x @ W^T, output quantized to fp16 -------------------------------
__global__ __launch_bounds__(256) void k_gemm_xw(
    const float* __restrict__ x, const float* __restrict__ W, int N)
{
    __shared__ float4 Wt[64][16];      // Wt[i][og] = {W[4og+0..3][i]}
    __shared__ float  xs[64][68];      // row stride 68 floats (16B aligned)

    int tid = threadIdx.x;
    int rg  = tid >> 4;                // 0..15
    int og  = tid & 15;                // 0..15
    int row0 = blockIdx.x * 64;

    #pragma unroll
    for (int idx = tid; idx < 64 * 16; idx += 256) {
        int i = idx >> 4, g = idx & 15;
        float4 w;
        w.x = W[(4 * g + 0) * 64 + i];
        w.y = W[(4 * g + 1) * 64 + i];
        w.z = W[(4 * g + 2) * 64 + i];
        w.w = W[(4 * g + 3) * 64 + i];
        Wt[i][g] = w;
    }
    #pragma unroll
    for (int idx = tid; idx < 64 * 16; idx += 256) {
        int r = idx >> 4, c4 = idx & 15;
        int gr = row0 + r;
        float4 v = (gr < N) ? *(const float4*)(x + (size_t)gr * 64 + c4 * 4)
                            : make_float4(0.f, 0.f, 0.f, 0.f);
        *(float4*)&xs[r][c4 * 4] = v;
    }
    __syncthreads();

    float4 acc[4];
    #pragma unroll
    for (int j = 0; j < 4; j++) acc[j] = make_float4(0.f, 0.f, 0.f, 0.f);

    #pragma unroll
    for (int i = 0; i < 64; i += 4) {
        float4 w0 = Wt[i + 0][og];
        float4 w1 = Wt[i + 1][og];
        float4 w2 = Wt[i + 2][og];
        float4 w3 = Wt[i + 3][og];
        #pragma unroll
        for (int j = 0; j < 4; j++) {
            float4 xv = *(const float4*)&xs[rg * 4 + j][i];
            acc[j].x += xv.x * w0.x + xv.y * w1.x + xv.z * w2.x + xv.w * w3.x;
            acc[j].y += xv.x * w0.y + xv.y * w1.y + xv.z * w2.y + xv.w * w3.y;
            acc[j].z += xv.x * w0.z + xv.y * w1.z + xv.z * w2.z + xv.w * w3.z;
            acc[j].w += xv.x * w0.w + xv.y * w1.w + xv.z * w2.w + xv.w * w3.w;
        }
    }

    #pragma unroll
    for (int j = 0; j < 4; j++) {
        int r = row0 + rg * 4 + j;
        if (r < N) {
            __half2 h0 = __floats2half2_rn(acc[j].x, acc[j].y);
            __half2 h1 = __floats2half2_rn(acc[j].z, acc[j].w);
            uint2 u;
            u.x = reinterpret_cast<unsigned&>(h0);
            u.y = reinterpret_cast<unsigned&>(h1);
            g_xwh[(size_t)r * 16 + og] = u;
        }
    }
}

// --- CSR aggregation: fp16 gather, fp32 accumulate, fused bias ------------
// 16 lanes per dst node; each lane owns 4 features.
__global__ __launch_bounds__(256) void k_agg_csr(
    float* __restrict__ out, const float* __restrict__ b, int N)
{
    int t    = blockIdx.x * 256 + threadIdx.x;
    int n    = t >> 4;
    int lane = t & 15;
    if (n >= N) return;

    int start = g_rows[n];
    int end   = g_rows[n + 1];

    float4 acc = make_float4(0.f, 0.f, 0.f, 0.f);
    int j = start;
    for (; j + 1 < end; j += 2) {                // unroll x2 for MLP
        uint2 e0 = g_csr[j];
        uint2 e1 = g_csr[j + 1];
        uint2 u0 = g_xwh[(size_t)e0.x * 16 + lane];
        uint2 u1 = g_xwh[(size_t)e1.x * 16 + lane];
        float w0 = __uint_as_float(e0.y);
        float w1 = __uint_as_float(e1.y);
        float2 a0 = __half22float2(reinterpret_cast<__half2&>(u0.x));
        float2 b0 = __half22float2(reinterpret_cast<__half2&>(u0.y));
        float2 a1 = __half22float2(reinterpret_cast<__half2&>(u1.x));
        float2 b1 = __half22float2(reinterpret_cast<__half2&>(u1.y));
        acc.x += w0 * a0.x + w1 * a1.x;
        acc.y += w0 * a0.y + w1 * a1.y;
        acc.z += w0 * b0.x + w1 * b1.x;
        acc.w += w0 * b0.y + w1 * b1.y;
    }
    if (j < end) {
        uint2 e0 = g_csr[j];
        uint2 u0 = g_xwh[(size_t)e0.x * 16 + lane];
        float w0 = __uint_as_float(e0.y);
        float2 a0 = __half22float2(reinterpret_cast<__half2&>(u0.x));
        float2 b0 = __half22float2(reinterpret_cast<__half2&>(u0.y));
        acc.x += w0 * a0.x;
        acc.y += w0 * a0.y;
        acc.z += w0 * b0.x;
        acc.w += w0 * b0.y;
    }

    float s = g_dinv_out[n];
    float4 bb = ((const float4*)b)[lane];
    float4 o;
    o.x = s * acc.x + bb.x;
    o.y = s * acc.y + bb.y;
    o.z = s * acc.z + bb.z;
    o.w = s * acc.w + bb.w;
    ((float4*)out)[(size_t)n * 16 + lane] = o;
}

// ---------------------------------------------------------------------------
extern "C" void kernel_launch(void* const* d_in, const int* in_sizes, int n_in,
                              void* d_out, int out_size)
{
    const float* x  = (const float*)d_in[0];
    const int*   ei = (const int*)d_in[1];     // int32 (JAX x64 disabled)
    const float* W  = (const float*)d_in[2];
    const float* b  = (const float*)d_in[3];
    float*       out = (float*)d_out;

    int N = in_sizes[0] / 64;
    int E = in_sizes[1] / 2;
    int nblocks = (N + 255) / 256;

    k_zero     <<<(N + 255) / 256, 256>>>(N);
    k_count_deg<<<(E + 255) / 256, 256>>>(ei, E);
    k_scan1    <<<nblocks, 256>>>(N);
    k_scan2    <<<1, NB_MAX>>>(nblocks);
    k_scan3    <<<(N + 255) / 256, 256>>>(N, E);
    k_scatter  <<<(E + 255) / 256, 256>>>(ei, E);
    k_gemm_xw  <<<(N + 63) / 64, 256>>>(x, W, N);
    k_agg_csr  <<<(N * 16 + 255) / 256, 256>>>(out, b, N);
}